// round 8
// baseline (speedup 1.0000x reference)
#include <cuda_runtime.h>
#include <cuda_bf16.h>

// ---------------------------------------------------------------------------
// AliasFreeActivation: bias -> up2x(12x12 FIR, pad10, gain4) -> lrelu*sqrt2,
// clamp(+-256) -> 12x12 FIR down2x.
// Input [8,128,128,128] f32 -> mid [264,264] -> out [8,128,127,127] f32.
//
// Block = 32x64 output tile of one plane, 384 threads.
// Filters live in __constant__ memory (uniform-port loads, zero L1 traffic).
// Mid parity-split (E,O) float2; all inner FMAs are packed fma.rn.f32x2.
// Odd-offset input pairs derived in registers (no second smem copy).
// ---------------------------------------------------------------------------

#define H      128
#define W      128
#define OHW    127
#define TY     32
#define TX     64
#define MIDH   74          // 2*TY+10
#define MSTR2  73          // mid row stride in float2 pairs
#define INH    43
#define INW    78          // even => 8B-aligned u64 rows; bank-pair step 7 mod 16
#define NTHREADS 384

#define S_IN_OFF   0
#define S_MID_OFF  3356                      // 43*78=3354, pad to even; byte 13424 (16B)
#define SMEM_FLOATS (S_MID_OFF + MIDH*MSTR2*2)  // 3356+10804 = 14160 -> 56640 B

typedef unsigned long long u64;

__constant__ __align__(16) float c_fu[144];
__constant__ __align__(16) float c_fd[144];

__device__ __forceinline__ u64 ffma2(u64 a, u64 b, u64 c) {
    u64 d;
    asm("fma.rn.f32x2 %0, %1, %2, %3;" : "=l"(d) : "l"(a), "l"(b), "l"(c));
    return d;
}
__device__ __forceinline__ u64 pack2(float lo, float hi) {
    u64 d;
    asm("mov.b64 %0, {%1, %2};" : "=l"(d) : "f"(lo), "f"(hi));
    return d;
}
__device__ __forceinline__ float2 unpack2(u64 d) {
    float2 f;
    asm("mov.b64 {%0, %1}, %2;" : "=f"(f.x), "=f"(f.y) : "l"(d));
    return f;
}

__global__ __launch_bounds__(NTHREADS, 2)
void afa_fused_kernel(const float* __restrict__ in,
                      const float* __restrict__ bias,
                      float* __restrict__ out)
{
    extern __shared__ float sm[];
    float* s_in  = sm + S_IN_OFF;
    float* s_mid = sm + S_MID_OFF;   // float2 pairs, stride MSTR2 per row

    const int tid   = threadIdx.x;
    const int b     = blockIdx.x;
    const int plane = b >> 3;
    const int t8    = b & 7;
    const int oy0   = (t8 >> 1) * TY;
    const int ox0   = (t8 & 1) * TX;
    const int iy0   = oy0 - 5;
    const int ix0   = ox0 - 5;

    const float bv = __ldg(&bias[plane & 127]);
    const float* __restrict__ inp = in + (size_t)plane * (H * W);

    // ---- Phase A: input tile (+bias, zero pad OOB) -------------------------
    for (int i = tid; i < INH * INW; i += NTHREADS) {
        const int r  = i / INW;
        const int cc = i - r * INW;
        const int gy = iy0 + r;
        const int gx = ix0 + cc;
        float v = 0.0f;
        if ((unsigned)gy < (unsigned)H && (unsigned)gx < (unsigned)W)
            v = __ldg(&inp[gy * W + gx]) + bv;
        s_in[i] = v;
    }
    __syncthreads();

    // ---- Phase B: polyphase up-conv (packed E,O) + activation -> MID2 ------
    // Parity-major job order: j<333 -> even mid rows, j>=333 -> odd rows, so
    // the filter row parity (hence its constant address) is warp-uniform.
    // Gain 4 (zero-insertion compensation) folded into activation gain G.
    const float G = 5.65685424949238019f;   // 4*sqrt(2)
    for (int j = tid; j < 666; j += NTHREADS) {
        const int p     = (j >= 333) ? 1 : 0;
        const int q     = j - 333 * p;        // 0..332
        const int chunk = q / 37;             // 0..8
        const int myh   = q - chunk * 37;     // 0..36
        const int my    = 2 * myh + p;
        const int j0    = chunk * 8;          // even pair/word column base

        u64 acc[8];
        #pragma unroll
        for (int jj = 0; jj < 8; jj++) acc[jj] = 0ull;

        #pragma unroll
        for (int t = 0; t < 6; t++) {
            const int rowoff = (myh + p + t) * INW + j0;   // even offset
            const u64* pa = (const u64*)(s_in + rowoff);
            u64 pe[7];
            #pragma unroll
            for (int m = 0; m < 7; m++) pe[m] = pa[m];
            u64 po[6];
            #pragma unroll
            for (int m = 0; m < 6; m++) {
                float2 lo = unpack2(pe[m]);
                float2 hi = unpack2(pe[m + 1]);
                po[m] = pack2(lo.y, hi.x);
            }

            const ulonglong2* fq = (const ulonglong2*)(c_fu + (2 * t + p) * 12);
            ulonglong2 f01 = fq[0], f23 = fq[1], f45 = fq[2];
            const u64 f0 = f01.x, f1 = f01.y, f2v = f23.x,
                      f3 = f23.y, f4 = f45.x, f5 = f45.y;

            #pragma unroll
            for (int jj = 0; jj < 8; jj++) {
                #define PR(a) (((a) & 1) ? po[(a) >> 1] : pe[(a) >> 1])
                acc[jj] = ffma2(PR(jj + 0), f0, acc[jj]);
                acc[jj] = ffma2(PR(jj + 1), f1, acc[jj]);
                acc[jj] = ffma2(PR(jj + 2), f2v, acc[jj]);
                acc[jj] = ffma2(PR(jj + 3), f3, acc[jj]);
                acc[jj] = ffma2(PR(jj + 4), f4, acc[jj]);
                acc[jj] = ffma2(PR(jj + 5), f5, acc[jj]);
                #undef PR
            }
        }
        // activation (gain folded) + store pair (E,O)
        float2* mrow = (float2*)s_mid + my * MSTR2 + j0;
        #pragma unroll
        for (int jj = 0; jj < 8; jj++) {
            float2 v = unpack2(acc[jj]);
            v.x = fminf(fmaxf(fmaxf(v.x, 0.2f * v.x) * G, -256.0f), 256.0f);
            v.y = fminf(fmaxf(fmaxf(v.y, 0.2f * v.y) * G, -256.0f), 256.0f);
            mrow[jj] = v;
        }
    }
    __syncthreads();

    // ---- Phase C: 12x12 down-conv stride 2, packed over (E,O) --------------
    // 12 warps: warp w -> row group rg=w>>1 (6 out rows), col half (w&1)*32.
    // lane = column. Each mid row feeds up to 6 accumulators; filter rows come
    // from constant memory at compile-time offsets (uniform port).
    {
        const int wrp  = tid >> 5;
        const int lane = tid & 31;
        const int rg   = wrp >> 1;                  // 0..5
        const int c    = ((wrp & 1) << 5) + lane;   // 0..63
        const int mbase = 12 * rg;
        const int mmMax = (rg == 5) ? 14 : 22;      // rg5 covers rows 30,31 only

        u64 acc[6];
        #pragma unroll
        for (int r = 0; r < 6; r++) acc[r] = 0ull;

        #pragma unroll
        for (int mm = 0; mm < 22; mm++) {
            if (mm >= mmMax) break;
            const u64* mrow = (const u64*)((float2*)s_mid + (mbase + mm) * MSTR2 + c);
            u64 md[6];
            #pragma unroll
            for (int s = 0; s < 6; s++) md[s] = mrow[s];

            const int rlo = (mm >= 12) ? ((mm - 10) >> 1) : 0;
            const int rhi = (mm >> 1) < 5 ? (mm >> 1) : 5;
            #pragma unroll
            for (int r = 0; r < 6; r++) {
                if (r < rlo || r > rhi) continue;       // folds at compile time
                const int ky = mm - 2 * r;              // compile-time constant
                const ulonglong2* fq = (const ulonglong2*)(c_fd + ky * 12);
                ulonglong2 f01 = fq[0], f23 = fq[1], f45 = fq[2];
                acc[r] = ffma2(md[0], f01.x, acc[r]);
                acc[r] = ffma2(md[1], f01.y, acc[r]);
                acc[r] = ffma2(md[2], f23.x, acc[r]);
                acc[r] = ffma2(md[3], f23.y, acc[r]);
                acc[r] = ffma2(md[4], f45.x, acc[r]);
                acc[r] = ffma2(md[5], f45.y, acc[r]);
            }
        }

        const int gx = ox0 + c;
        if (gx < OHW) {
            float* op = out + (size_t)plane * (OHW * OHW) + gx;
            #pragma unroll
            for (int r = 0; r < 6; r++) {
                const int orow = rg * 6 + r;
                const int gy = oy0 + orow;
                if (orow < TY && gy < OHW) {
                    float2 v = unpack2(acc[r]);
                    op[gy * OHW] = v.x + v.y;
                }
            }
        }
    }
}

extern "C" void kernel_launch(void* const* d_in, const int* in_sizes, int n_in,
                              void* d_out, int out_size)
{
    const float* in   = (const float*)d_in[0];
    const float* bias = (const float*)d_in[1];
    const float* fu   = (const float*)d_in[2];
    const float* fd   = (const float*)d_in[3];
    float* out        = (float*)d_out;

    // Filters into constant memory (async D2D copies: graph-capturable).
    cudaMemcpyToSymbolAsync(c_fu, fu, 144 * sizeof(float), 0,
                            cudaMemcpyDeviceToDevice, 0);
    cudaMemcpyToSymbolAsync(c_fd, fd, 144 * sizeof(float), 0,
                            cudaMemcpyDeviceToDevice, 0);

    const size_t smem = SMEM_FLOATS * sizeof(float);   // 56640 B
    cudaFuncSetAttribute(afa_fused_kernel,
                         cudaFuncAttributeMaxDynamicSharedMemorySize, (int)smem);

    const int nblocks = 1024 * 8;
    afa_fused_kernel<<<nblocks, NTHREADS, smem>>>(in, bias, out);
}

// round 9
// speedup vs baseline: 1.1320x; 1.1320x over previous
#include <cuda_runtime.h>
#include <cuda_bf16.h>

// ---------------------------------------------------------------------------
// AliasFreeActivation: bias -> up2x(12x12 FIR, pad10, gain4) -> lrelu*sqrt2,
// clamp(+-256) -> 12x12 FIR down2x.
// Input [8,128,128,128] f32 -> mid [264,264] -> out [8,128,127,127] f32.
//
// Block = 32x64 output tile of one plane, 384 threads.
// Filters in __constant__ memory (uniform-port loads, zero L1 traffic).
// Input stored twice (sA = row, sB = row shifted 1): every overlapping pair
// is a direct aligned LDS.64 (no packing MOVs). Mid parity-split (E,O)
// float2. All inner FMAs are packed fma.rn.f32x2.
// ---------------------------------------------------------------------------

#define H      128
#define W      128
#define OHW    127
#define TY     32
#define TX     64
#define MIDH   74          // 2*TY+10
#define MSTR2  73          // mid row stride in float2 pairs
#define INH    43
#define INW    78          // even => 8B-aligned u64 rows; bank-pair step 7 mod 16
#define NTHREADS 384

#define S_SA_OFF   0
#define S_SB_OFF   (INH*INW)                    // 3354 (even -> 8B aligned)
#define S_MID_OFF  (2*INH*INW)                  // 6708 (byte 26832, 16B aligned)
#define SMEM_FLOATS (S_MID_OFF + MIDH*MSTR2*2)  // 6708+10804 = 17512 -> 70048 B

typedef unsigned long long u64;

__constant__ __align__(16) float c_fu[144];
__constant__ __align__(16) float c_fd[144];

__device__ __forceinline__ u64 ffma2(u64 a, u64 b, u64 c) {
    u64 d;
    asm("fma.rn.f32x2 %0, %1, %2, %3;" : "=l"(d) : "l"(a), "l"(b), "l"(c));
    return d;
}
__device__ __forceinline__ float2 unpack2(u64 d) {
    float2 f;
    asm("mov.b64 {%0, %1}, %2;" : "=f"(f.x), "=f"(f.y) : "l"(d));
    return f;
}

__global__ __launch_bounds__(NTHREADS, 2)
void afa_fused_kernel(const float* __restrict__ in,
                      const float* __restrict__ bias,
                      float* __restrict__ out)
{
    extern __shared__ float sm[];
    float* s_sa  = sm + S_SA_OFF;
    float* s_sb  = sm + S_SB_OFF;
    float* s_mid = sm + S_MID_OFF;   // float2 pairs, stride MSTR2 per row

    const int tid   = threadIdx.x;
    const int b     = blockIdx.x;
    const int plane = b >> 3;
    const int t8    = b & 7;
    const int oy0   = (t8 >> 1) * TY;
    const int ox0   = (t8 & 1) * TX;
    const int iy0   = oy0 - 5;
    const int ix0   = ox0 - 5;

    const float bv = __ldg(&bias[plane & 127]);
    const float* __restrict__ inp = in + (size_t)plane * (H * W);

    // ---- Phase A: dual input copies (+bias, zero pad OOB) ------------------
    for (int i = tid; i < INH * INW; i += NTHREADS) {
        const int r  = i / INW;
        const int cc = i - r * INW;
        const int gy = iy0 + r;
        const int gx = ix0 + cc;
        float v = 0.0f;
        if ((unsigned)gy < (unsigned)H && (unsigned)gx < (unsigned)W)
            v = __ldg(&inp[gy * W + gx]) + bv;
        s_sa[i] = v;                       // sA[w] = x[w]
        if (cc > 0) s_sb[i - 1] = v;       // sB[w] = x[w+1]
    }
    __syncthreads();

    // ---- Phase B: polyphase up-conv (packed E,O) + activation -> MID2 ------
    // Parity-major job order: j<333 -> even mid rows, j>=333 -> odd rows, so
    // the up-filter row address is warp-uniform (uniform-port friendly).
    // Gain 4 (zero-insertion compensation) folded into activation gain G.
    const float G = 5.65685424949238019f;   // 4*sqrt(2)
    for (int j = tid; j < 666; j += NTHREADS) {
        const int p     = (j >= 333) ? 1 : 0;
        const int q     = j - 333 * p;        // 0..332
        const int chunk = q / 37;             // 0..8
        const int myh   = q - chunk * 37;     // 0..36
        const int my    = 2 * myh + p;
        const int j0    = chunk * 8;          // even pair/word column base

        u64 acc[8];
        #pragma unroll
        for (int jj = 0; jj < 8; jj++) acc[jj] = 0ull;

        #pragma unroll
        for (int t = 0; t < 6; t++) {
            const int rowoff = (myh + p + t) * INW + j0;   // even offset
            const u64* pa = (const u64*)(s_sa + rowoff);   // (x[a],x[a+1]), a even
            const u64* pb = (const u64*)(s_sb + rowoff);   // (x[a],x[a+1]), a odd
            u64 pe[7], po[6];
            #pragma unroll
            for (int m = 0; m < 7; m++) pe[m] = pa[m];
            #pragma unroll
            for (int m = 0; m < 6; m++) po[m] = pb[m];

            const ulonglong2* fq = (const ulonglong2*)(c_fu + (2 * t + p) * 12);
            ulonglong2 f01 = fq[0], f23 = fq[1], f45 = fq[2];
            const u64 f0 = f01.x, f1 = f01.y, f2v = f23.x,
                      f3 = f23.y, f4 = f45.x, f5 = f45.y;

            #pragma unroll
            for (int jj = 0; jj < 8; jj++) {
                #define PR(a) (((a) & 1) ? po[(a) >> 1] : pe[(a) >> 1])
                acc[jj] = ffma2(PR(jj + 0), f0, acc[jj]);
                acc[jj] = ffma2(PR(jj + 1), f1, acc[jj]);
                acc[jj] = ffma2(PR(jj + 2), f2v, acc[jj]);
                acc[jj] = ffma2(PR(jj + 3), f3, acc[jj]);
                acc[jj] = ffma2(PR(jj + 4), f4, acc[jj]);
                acc[jj] = ffma2(PR(jj + 5), f5, acc[jj]);
                #undef PR
            }
        }
        // activation (gain folded) + store pair (E,O)
        float2* mrow = (float2*)s_mid + my * MSTR2 + j0;
        #pragma unroll
        for (int jj = 0; jj < 8; jj++) {
            float2 v = unpack2(acc[jj]);
            v.x = fminf(fmaxf(fmaxf(v.x, 0.2f * v.x) * G, -256.0f), 256.0f);
            v.y = fminf(fmaxf(fmaxf(v.y, 0.2f * v.y) * G, -256.0f), 256.0f);
            mrow[jj] = v;
        }
    }
    __syncthreads();

    // ---- Phase C: 12x12 down-conv stride 2, packed over (E,O) --------------
    // 12 warps: warp w -> row group rg=w>>1 (6 out rows), col half (w&1)*32.
    // lane = column. Each mid row feeds up to 6 accumulators; filter rows come
    // from constant memory at compile-time offsets (uniform port).
    {
        const int wrp  = tid >> 5;
        const int lane = tid & 31;
        const int rg   = wrp >> 1;                  // 0..5
        const int c    = ((wrp & 1) << 5) + lane;   // 0..63
        const int mbase = 12 * rg;
        const int mmMax = (rg == 5) ? 14 : 22;      // rg5 covers rows 30,31 only

        u64 acc[6];
        #pragma unroll
        for (int r = 0; r < 6; r++) acc[r] = 0ull;

        #pragma unroll
        for (int mm = 0; mm < 22; mm++) {
            if (mm >= mmMax) break;
            const u64* mrow = (const u64*)((float2*)s_mid + (mbase + mm) * MSTR2 + c);
            u64 md[6];
            #pragma unroll
            for (int s = 0; s < 6; s++) md[s] = mrow[s];

            const int rlo = (mm >= 12) ? ((mm - 10) >> 1) : 0;
            const int rhi = (mm >> 1) < 5 ? (mm >> 1) : 5;
            #pragma unroll
            for (int r = 0; r < 6; r++) {
                if (r < rlo || r > rhi) continue;       // folds at compile time
                const int ky = mm - 2 * r;              // compile-time constant
                const ulonglong2* fq = (const ulonglong2*)(c_fd + ky * 12);
                ulonglong2 f01 = fq[0], f23 = fq[1], f45 = fq[2];
                acc[r] = ffma2(md[0], f01.x, acc[r]);
                acc[r] = ffma2(md[1], f01.y, acc[r]);
                acc[r] = ffma2(md[2], f23.x, acc[r]);
                acc[r] = ffma2(md[3], f23.y, acc[r]);
                acc[r] = ffma2(md[4], f45.x, acc[r]);
                acc[r] = ffma2(md[5], f45.y, acc[r]);
            }
        }

        const int gx = ox0 + c;
        if (gx < OHW) {
            float* op = out + (size_t)plane * (OHW * OHW) + gx;
            #pragma unroll
            for (int r = 0; r < 6; r++) {
                const int orow = rg * 6 + r;
                const int gy = oy0 + orow;
                if (orow < TY && gy < OHW) {
                    float2 v = unpack2(acc[r]);
                    op[gy * OHW] = v.x + v.y;
                }
            }
        }
    }
}

extern "C" void kernel_launch(void* const* d_in, const int* in_sizes, int n_in,
                              void* d_out, int out_size)
{
    const float* in   = (const float*)d_in[0];
    const float* bias = (const float*)d_in[1];
    const float* fu   = (const float*)d_in[2];
    const float* fd   = (const float*)d_in[3];
    float* out        = (float*)d_out;

    // Filters into constant memory (async D2D copies: graph-capturable).
    cudaMemcpyToSymbolAsync(c_fu, fu, 144 * sizeof(float), 0,
                            cudaMemcpyDeviceToDevice, 0);
    cudaMemcpyToSymbolAsync(c_fd, fd, 144 * sizeof(float), 0,
                            cudaMemcpyDeviceToDevice, 0);

    const size_t smem = SMEM_FLOATS * sizeof(float);   // 70048 B
    cudaFuncSetAttribute(afa_fused_kernel,
                         cudaFuncAttributeMaxDynamicSharedMemorySize, (int)smem);

    const int nblocks = 1024 * 8;
    afa_fused_kernel<<<nblocks, NTHREADS, smem>>>(in, bias, out);
}

// round 10
// speedup vs baseline: 1.2653x; 1.1177x over previous
#include <cuda_runtime.h>
#include <cuda_bf16.h>

// ---------------------------------------------------------------------------
// AliasFreeActivation: bias -> up2x(12x12 FIR, pad10, gain4) -> lrelu*sqrt2,
// clamp(+-256) -> 12x12 FIR down2x.
// Input [8,128,128,128] f32 -> mid [264,264] -> out [8,128,127,127] f32.
//
// Block = 32x64 output tile, 384 threads. Filters in __constant__ (uniform
// port). Input stored twice (sA, sB=shift-1) so overlapping pairs are direct
// LDS.64. Phase B computes an (even,odd) mid-row PAIR per job: the 7 shared
// input rows are loaded once and feed both rows (-42% input loads). Mid is
// parity-split into even/odd half-arrays (conflict-free stride-73 stores).
// All inner FMAs are packed fma.rn.f32x2.
// ---------------------------------------------------------------------------

#define H      128
#define W      128
#define OHW    127
#define TY     32
#define TX     64
#define MSTR2  73          // half-mid row stride in (E,O) float2 pairs
#define INH    43
#define INW    78          // even => 8B-aligned u64 rows; u64 stride 39%16==7
#define NTHREADS 384

#define S_SA_OFF    0
#define S_SB_OFF    (INH*INW)                   // 3354
#define S_MIDE_OFF  (2*INH*INW)                 // 6708  (byte 26832, 16B)
#define S_MIDO_OFF  (S_MIDE_OFF + 37*MSTR2*2)   // 6708+5402 = 12110
#define SMEM_FLOATS (S_MIDO_OFF + 37*MSTR2*2)   // 17512 -> 70048 B

typedef unsigned long long u64;

__constant__ __align__(16) float c_fu[144];
__constant__ __align__(16) float c_fd[144];

__device__ __forceinline__ u64 ffma2(u64 a, u64 b, u64 c) {
    u64 d;
    asm("fma.rn.f32x2 %0, %1, %2, %3;" : "=l"(d) : "l"(a), "l"(b), "l"(c));
    return d;
}
__device__ __forceinline__ float2 unpack2(u64 d) {
    float2 f;
    asm("mov.b64 {%0, %1}, %2;" : "=f"(f.x), "=f"(f.y) : "l"(d));
    return f;
}

__global__ __launch_bounds__(NTHREADS, 2)
void afa_fused_kernel(const float* __restrict__ in,
                      const float* __restrict__ bias,
                      float* __restrict__ out)
{
    extern __shared__ float sm[];
    float* s_sa   = sm + S_SA_OFF;
    float* s_sb   = sm + S_SB_OFF;
    u64*   s_midE = (u64*)(sm + S_MIDE_OFF);   // even mid rows, (E,O) pairs
    u64*   s_midO = (u64*)(sm + S_MIDO_OFF);   // odd  mid rows

    const int tid   = threadIdx.x;
    const int b     = blockIdx.x;
    const int plane = b >> 3;
    const int t8    = b & 7;
    const int oy0   = (t8 >> 1) * TY;
    const int ox0   = (t8 & 1) * TX;
    const int iy0   = oy0 - 5;
    const int ix0   = ox0 - 5;

    const float bv = __ldg(&bias[plane & 127]);
    const float* __restrict__ inp = in + (size_t)plane * (H * W);

    // ---- Phase A: dual input copies (+bias, zero pad OOB) ------------------
    for (int i = tid; i < INH * INW; i += NTHREADS) {
        const int r  = i / INW;
        const int cc = i - r * INW;
        const int gy = iy0 + r;
        const int gx = ix0 + cc;
        float v = 0.0f;
        if ((unsigned)gy < (unsigned)H && (unsigned)gx < (unsigned)W)
            v = __ldg(&inp[gy * W + gx]) + bv;
        s_sa[i] = v;                       // sA[w] = x[w]
        if (cc > 0) s_sb[i - 1] = v;       // sB[w] = x[w+1]
    }
    __syncthreads();

    // ---- Phase B: row-PAIR polyphase up-conv + activation ------------------
    // Job tid<333: mid rows (2q, 2q+1), 16 columns (8 E/O pairs).
    // Shared input rows q..q+6 loaded once; even row uses fu row 2t (t<6),
    // odd row uses fu row 2t-1 (t>=1). Filter offsets are compile-time.
    // Gain 4 folded into activation gain G.
    const float G = 5.65685424949238019f;   // 4*sqrt(2)
    if (tid < 333) {
        const int chunk = tid / 37;           // 0..8
        const int q     = tid - chunk * 37;   // 0..36
        const int j0    = chunk * 8;          // pair/word column base (even)

        u64 ae[8], ao[8];
        #pragma unroll
        for (int jj = 0; jj < 8; jj++) { ae[jj] = 0ull; ao[jj] = 0ull; }

        #pragma unroll
        for (int t = 0; t < 7; t++) {
            const int rowoff = (q + t) * INW + j0;         // even offset
            const u64* pa = (const u64*)(s_sa + rowoff);   // (x[a],x[a+1]), a even
            const u64* pb = (const u64*)(s_sb + rowoff);   // (x[a],x[a+1]), a odd
            u64 pe[7], po[6];
            #pragma unroll
            for (int m = 0; m < 7; m++) pe[m] = pa[m];
            #pragma unroll
            for (int m = 0; m < 6; m++) po[m] = pb[m];

            #define PR(a) (((a) & 1) ? po[(a) >> 1] : pe[(a) >> 1])
            if (t < 6) {   // even mid row, filter row 2t (compile-time)
                const ulonglong2* fq = (const ulonglong2*)(c_fu + (2 * t) * 12);
                ulonglong2 f01 = fq[0], f23 = fq[1], f45 = fq[2];
                #pragma unroll
                for (int jj = 0; jj < 8; jj++) {
                    ae[jj] = ffma2(PR(jj + 0), f01.x, ae[jj]);
                    ae[jj] = ffma2(PR(jj + 1), f01.y, ae[jj]);
                    ae[jj] = ffma2(PR(jj + 2), f23.x, ae[jj]);
                    ae[jj] = ffma2(PR(jj + 3), f23.y, ae[jj]);
                    ae[jj] = ffma2(PR(jj + 4), f45.x, ae[jj]);
                    ae[jj] = ffma2(PR(jj + 5), f45.y, ae[jj]);
                }
            }
            if (t >= 1) {  // odd mid row, filter row 2t-1 (compile-time)
                const ulonglong2* fq = (const ulonglong2*)(c_fu + (2 * t - 1) * 12);
                ulonglong2 f01 = fq[0], f23 = fq[1], f45 = fq[2];
                #pragma unroll
                for (int jj = 0; jj < 8; jj++) {
                    ao[jj] = ffma2(PR(jj + 0), f01.x, ao[jj]);
                    ao[jj] = ffma2(PR(jj + 1), f01.y, ao[jj]);
                    ao[jj] = ffma2(PR(jj + 2), f23.x, ao[jj]);
                    ao[jj] = ffma2(PR(jj + 3), f23.y, ao[jj]);
                    ao[jj] = ffma2(PR(jj + 4), f45.x, ao[jj]);
                    ao[jj] = ffma2(PR(jj + 5), f45.y, ao[jj]);
                }
            }
            #undef PR
        }
        // activation (gain folded) + store pairs; stride 73 u64 (9 mod 16)
        u64* re = s_midE + q * MSTR2 + j0;
        u64* ro = s_midO + q * MSTR2 + j0;
        #pragma unroll
        for (int jj = 0; jj < 8; jj++) {
            float2 v = unpack2(ae[jj]);
            v.x = fminf(fmaxf(fmaxf(v.x, 0.2f * v.x) * G, -256.0f), 256.0f);
            v.y = fminf(fmaxf(fmaxf(v.y, 0.2f * v.y) * G, -256.0f), 256.0f);
            ((float2*)re)[jj] = v;
            float2 w = unpack2(ao[jj]);
            w.x = fminf(fmaxf(fmaxf(w.x, 0.2f * w.x) * G, -256.0f), 256.0f);
            w.y = fminf(fmaxf(fmaxf(w.y, 0.2f * w.y) * G, -256.0f), 256.0f);
            ((float2*)ro)[jj] = w;
        }
    }
    __syncthreads();

    // ---- Phase C: 12x12 down-conv stride 2, packed over (E,O) --------------
    // 12 warps: warp w -> row group rg=w>>1 (6 out rows), col half (w&1)*32.
    // lane = column. Mid row (12rg+mm): parity mm&1 selects the half-array,
    // half-row index = 6rg + (mm>>1). Filter rows from constant memory.
    {
        const int wrp  = tid >> 5;
        const int lane = tid & 31;
        const int rg   = wrp >> 1;                  // 0..5
        const int c    = ((wrp & 1) << 5) + lane;   // 0..63
        const int mmMax = (rg == 5) ? 14 : 22;      // rg5 covers rows 30,31 only
        const u64* hb = s_midE + 6 * rg * MSTR2 + c;
        const u64* ob = s_midO + 6 * rg * MSTR2 + c;

        u64 acc[6];
        #pragma unroll
        for (int r = 0; r < 6; r++) acc[r] = 0ull;

        #pragma unroll
        for (int mm = 0; mm < 22; mm++) {
            if (mm >= mmMax) break;
            const u64* mrow = ((mm & 1) ? ob : hb) + (mm >> 1) * MSTR2;
            u64 md[6];
            #pragma unroll
            for (int s = 0; s < 6; s++) md[s] = mrow[s];

            const int rlo = (mm >= 12) ? ((mm - 10) >> 1) : 0;
            const int rhi = (mm >> 1) < 5 ? (mm >> 1) : 5;
            #pragma unroll
            for (int r = 0; r < 6; r++) {
                if (r < rlo || r > rhi) continue;       // folds at compile time
                const int ky = mm - 2 * r;              // compile-time constant
                const ulonglong2* fq = (const ulonglong2*)(c_fd + ky * 12);
                ulonglong2 f01 = fq[0], f23 = fq[1], f45 = fq[2];
                acc[r] = ffma2(md[0], f01.x, acc[r]);
                acc[r] = ffma2(md[1], f01.y, acc[r]);
                acc[r] = ffma2(md[2], f23.x, acc[r]);
                acc[r] = ffma2(md[3], f23.y, acc[r]);
                acc[r] = ffma2(md[4], f45.x, acc[r]);
                acc[r] = ffma2(md[5], f45.y, acc[r]);
            }
        }

        const int gx = ox0 + c;
        if (gx < OHW) {
            float* op = out + (size_t)plane * (OHW * OHW) + gx;
            #pragma unroll
            for (int r = 0; r < 6; r++) {
                const int orow = rg * 6 + r;
                const int gy = oy0 + orow;
                if (orow < TY && gy < OHW) {
                    float2 v = unpack2(acc[r]);
                    op[gy * OHW] = v.x + v.y;
                }
            }
        }
    }
}

extern "C" void kernel_launch(void* const* d_in, const int* in_sizes, int n_in,
                              void* d_out, int out_size)
{
    const float* in   = (const float*)d_in[0];
    const float* bias = (const float*)d_in[1];
    const float* fu   = (const float*)d_in[2];
    const float* fd   = (const float*)d_in[3];
    float* out        = (float*)d_out;

    // Filters into constant memory (async D2D copies: graph-capturable).
    cudaMemcpyToSymbolAsync(c_fu, fu, 144 * sizeof(float), 0,
                            cudaMemcpyDeviceToDevice, 0);
    cudaMemcpyToSymbolAsync(c_fd, fd, 144 * sizeof(float), 0,
                            cudaMemcpyDeviceToDevice, 0);

    const size_t smem = SMEM_FLOATS * sizeof(float);   // 70048 B
    cudaFuncSetAttribute(afa_fused_kernel,
                         cudaFuncAttributeMaxDynamicSharedMemorySize, (int)smem);

    const int nblocks = 1024 * 8;
    afa_fused_kernel<<<nblocks, NTHREADS, smem>>>(in, bias, out);
}